// round 3
// baseline (speedup 1.0000x reference)
#include <cuda_runtime.h>
#include <math.h>

#define H      2048
#define HH     1024
#define BATCH  4
#define SEQ    4096
#define M_ROWS 16384   // BATCH * SEQ
#define SUPC   4
#define HEADSC 8

// d_out float offsets (tuple order, flattened)
#define OFF_TOK  0
#define OFF_CTX  16384
#define OFF_TASK 16388
#define OFF_SUP  16392
#define OFF_DEP  81928
#define OFF_EFF  213000
#define OFF_MASK 229384

// ---------------- scratch (no allocations allowed) ----------------
__device__ float g_ctxsum[BATCH * H];        // sum over S (divide later)
__device__ float g_rowsum[2][M_ROWS];        // tok / eff pre-sigmoid sums
__device__ float g_slog[M_ROWS * SUPC];      // sup logits (no bias yet)
__device__ float g_dlog[M_ROWS * HEADSC];    // dep logits (no bias yet)

__device__ __forceinline__ float gelu_exact(float x) {
    return 0.5f * x * (1.0f + erff(x * 0.70710678118654752f));
}
__device__ __forceinline__ float sigmoidf_(float x) {
    return 1.0f / (1.0f + expf(-x));
}

// ---------------- zero scratch each launch (graph-replay safe) ----------------
__global__ void zero_scratch() {
    int i = blockIdx.x * blockDim.x + threadIdx.x;
    if (i < BATCH * H)        g_ctxsum[i] = 0.f;
    if (i < 2 * M_ROWS)       (&g_rowsum[0][0])[i] = 0.f;
    if (i < M_ROWS * SUPC)    g_slog[i] = 0.f;
    if (i < M_ROWS * HEADSC)  g_dlog[i] = 0.f;
}

// ---------------- context mean: partial sums over S ----------------
__global__ void mean_partial(const float* __restrict__ X) {
    int idx = blockIdx.x * blockDim.x + threadIdx.x;   // 131072 threads
    int d     = idx & (H - 1);
    int chunk = (idx >> 11) & 15;
    int b     = idx >> 15;
    const float* p = X + ((size_t)(b * SEQ + chunk * 256)) * H + d;
    float s = 0.f;
    #pragma unroll 8
    for (int t = 0; t < 256; t++) s += p[(size_t)t * H];
    atomicAdd(&g_ctxsum[b * H + d], s);
}

// ---------------- ctx / task MLPs (tiny) ----------------
__global__ void ctx_task_kernel(
    const float* __restrict__ cW1, const float* __restrict__ cb1,
    const float* __restrict__ cW2, const float* __restrict__ cb2,
    const float* __restrict__ tW1, const float* __restrict__ tb1,
    const float* __restrict__ tW2, const float* __restrict__ tb2,
    float* __restrict__ out)
{
    __shared__ float emb[H];
    __shared__ float red[1024];
    int b = blockIdx.x, which = blockIdx.y;
    const float* W1 = which ? tW1 : cW1;
    const float* b1 = which ? tb1 : cb1;
    const float* W2 = which ? tW2 : cW2;
    const float* b2 = which ? tb2 : cb2;
    int tid = threadIdx.x;   // 1024 threads, one hidden unit each
    for (int i = tid; i < H; i += 1024)
        emb[i] = g_ctxsum[b * H + i] * (1.0f / SEQ);
    __syncthreads();

    float a = b1[tid];
    #pragma unroll 4
    for (int k = 0; k < H; k++)
        a = fmaf(emb[k], W1[(size_t)k * HH + tid], a);
    red[tid] = gelu_exact(a) * W2[tid];
    __syncthreads();
    for (int off = 512; off > 0; off >>= 1) {
        if (tid < off) red[tid] += red[tid + off];
        __syncthreads();
    }
    if (tid == 0)
        out[(which ? OFF_TASK : OFF_CTX) + b] = sigmoidf_(red[0] + b2[0]);
}

// ---------------- fused MLP GEMM ----------------
// Computes a BM x BN tile of h = X @ W1 (K=2048), adds b1 (+ optional extra
// features tc/cc/tk using W1 rows 2048..2050), applies exact GELU, then
// reduces h @ W2 (N x C) into per-row logits via warp shuffles + atomicAdd.
// dst: 0 -> g_rowsum[0], 1 -> g_rowsum[1], 2 -> g_slog, 3 -> g_dlog
template <int C, bool EX>
__global__ __launch_bounds__(256)
void mlp_gemm(const float* __restrict__ X, const float* __restrict__ W1,
              const float* __restrict__ b1, const float* __restrict__ W2,
              int dst, const float* __restrict__ tcv,
              const float* __restrict__ ccv, const float* __restrict__ tkv,
              int N)
{
    __shared__ float As[16][132];   // [k][m], padded
    __shared__ float Bs[16][64];    // [k][n]

    float* accout;
    if      (dst == 0) accout = g_rowsum[0];
    else if (dst == 1) accout = g_rowsum[1];
    else if (dst == 2) accout = g_slog;
    else               accout = g_dlog;

    const int tid  = threadIdx.x;
    const int tx   = tid & 15;       // 16 cols of 4
    const int ty   = tid >> 4;       // 16 rows of 8
    const int row0 = blockIdx.y * 128;
    const int n0   = blockIdx.x * 64;

    float acc[8][4];
    #pragma unroll
    for (int i = 0; i < 8; i++)
        #pragma unroll
        for (int j = 0; j < 4; j++) acc[i][j] = 0.f;

    // A loader mapping: float4 index i -> m = i>>2, k = (i&3)*4
    const int am0 = tid >> 2;
    const int ak0 = (tid & 3) * 4;
    const float* Aptr0 = X + (size_t)(row0 + am0) * H + ak0;
    const float* Aptr1 = X + (size_t)(row0 + am0 + 64) * H + ak0;
    // B loader mapping: k = tid>>4, n = (tid&15)*4
    const int bk0 = tid >> 4;
    const int bn0 = (tid & 15) * 4;
    const float* Bptr = W1 + (size_t)bk0 * N + n0 + bn0;

    float4 a0 = *(const float4*)Aptr0;
    float4 a1 = *(const float4*)Aptr1;
    float4 bb = *(const float4*)Bptr;

    const int KT = H / 16;
    for (int kt = 0; kt < KT; kt++) {
        As[ak0 + 0][am0] = a0.x; As[ak0 + 1][am0] = a0.y;
        As[ak0 + 2][am0] = a0.z; As[ak0 + 3][am0] = a0.w;
        As[ak0 + 0][am0 + 64] = a1.x; As[ak0 + 1][am0 + 64] = a1.y;
        As[ak0 + 2][am0 + 64] = a1.z; As[ak0 + 3][am0 + 64] = a1.w;
        *(float4*)&Bs[bk0][bn0] = bb;
        __syncthreads();

        if (kt + 1 < KT) {
            a0 = *(const float4*)(Aptr0 + (kt + 1) * 16);
            a1 = *(const float4*)(Aptr1 + (kt + 1) * 16);
            bb = *(const float4*)(Bptr + (size_t)(kt + 1) * 16 * N);
        }

        #pragma unroll
        for (int k = 0; k < 16; k++) {
            float4 t0 = *(const float4*)&As[k][ty * 8];
            float4 t1 = *(const float4*)&As[k][ty * 8 + 4];
            float4 tb = *(const float4*)&Bs[k][tx * 4];
            float ar[8] = {t0.x, t0.y, t0.z, t0.w, t1.x, t1.y, t1.z, t1.w};
            float br[4] = {tb.x, tb.y, tb.z, tb.w};
            #pragma unroll
            for (int i = 0; i < 8; i++)
                #pragma unroll
                for (int j = 0; j < 4; j++)
                    acc[i][j] = fmaf(ar[i], br[j], acc[i][j]);
        }
        __syncthreads();
    }

    // ---------------- epilogue ----------------
    const int jg0 = n0 + tx * 4;
    float b1v[4];
    #pragma unroll
    for (int jj = 0; jj < 4; jj++) b1v[jj] = b1[jg0 + jj];

    float tcr[8];
    float ccs = 0.f, tks = 0.f;
    float e0[4], e1[4], e2[4];
    if (EX) {
        int b = row0 >> 12;   // 4096 rows per batch, BM=128 divides
        ccs = ccv[b]; tks = tkv[b];
        #pragma unroll
        for (int i = 0; i < 8; i++) tcr[i] = tcv[row0 + ty * 8 + i];
        #pragma unroll
        for (int jj = 0; jj < 4; jj++) {
            e0[jj] = W1[(size_t)H * N + jg0 + jj];
            e1[jj] = W1[(size_t)(H + 1) * N + jg0 + jj];
            e2[jj] = W1[(size_t)(H + 2) * N + jg0 + jj];
        }
    }

    float w2r[4][C];
    #pragma unroll
    for (int jj = 0; jj < 4; jj++)
        #pragma unroll
        for (int c = 0; c < C; c++)
            w2r[jj][c] = W2[(size_t)(jg0 + jj) * C + c];

    #pragma unroll
    for (int i = 0; i < 8; i++) {
        const int r = row0 + ty * 8 + i;
        float pc[C];
        #pragma unroll
        for (int c = 0; c < C; c++) pc[c] = 0.f;
        #pragma unroll
        for (int jj = 0; jj < 4; jj++) {
            float v = acc[i][jj] + b1v[jj];
            if (EX) v += tcr[i] * e0[jj] + ccs * e1[jj] + tks * e2[jj];
            float h = gelu_exact(v);
            #pragma unroll
            for (int c = 0; c < C; c++) pc[c] = fmaf(h, w2r[jj][c], pc[c]);
        }
        #pragma unroll
        for (int c = 0; c < C; c++) {
            float v = pc[c];
            v += __shfl_xor_sync(0xffffffffu, v, 8);
            v += __shfl_xor_sync(0xffffffffu, v, 4);
            v += __shfl_xor_sync(0xffffffffu, v, 2);
            v += __shfl_xor_sync(0xffffffffu, v, 1);
            if (tx == 0) atomicAdd(&accout[(size_t)r * C + c], v);
        }
    }
}

// ---------------- tok / eff finalize ----------------
__global__ void finalize_tokeff(float* __restrict__ out,
                                const float* __restrict__ tokb2,
                                const float* __restrict__ effb2)
{
    int r = blockIdx.x * blockDim.x + threadIdx.x;
    if (r < M_ROWS) {
        out[OFF_TOK + r] = sigmoidf_(g_rowsum[0][r] + tokb2[0]);
        out[OFF_EFF + r] = sigmoidf_(g_rowsum[1][r] + effb2[0]);
    }
}

// ---------------- softmax + mask ----------------
__global__ void softmax_mask(float* __restrict__ out,
                             const float* __restrict__ supb2,
                             const float* __restrict__ depb2)
{
    int r = blockIdx.x * blockDim.x + threadIdx.x;
    if (r >= M_ROWS) return;

    // superposition softmax (4) + mask
    {
        float l[SUPC];
        float m = -1e30f;
        #pragma unroll
        for (int c = 0; c < SUPC; c++) {
            l[c] = g_slog[(size_t)r * SUPC + c] + supb2[c];
            m = fmaxf(m, l[c]);
        }
        float s = 0.f;
        #pragma unroll
        for (int c = 0; c < SUPC; c++) { l[c] = expf(l[c] - m); s += l[c]; }
        float inv = 1.f / s;
        float eff = out[OFF_EFF + r];
        #pragma unroll
        for (int c = 0; c < SUPC; c++) {
            float w = l[c] * inv;
            out[OFF_SUP  + (size_t)r * SUPC + c] = w;
            out[OFF_MASK + (size_t)r * SUPC + c] = (w > 0.2f) ? eff : 0.f;
        }
    }
    // depth softmax (8)
    {
        float l[HEADSC];
        float m = -1e30f;
        #pragma unroll
        for (int c = 0; c < HEADSC; c++) {
            l[c] = g_dlog[(size_t)r * HEADSC + c] + depb2[c];
            m = fmaxf(m, l[c]);
        }
        float s = 0.f;
        #pragma unroll
        for (int c = 0; c < HEADSC; c++) { l[c] = expf(l[c] - m); s += l[c]; }
        float inv = 1.f / s;
        #pragma unroll
        for (int c = 0; c < HEADSC; c++)
            out[OFF_DEP + (size_t)r * HEADSC + c] = l[c] * inv;
    }
}

// ---------------- launch ----------------
extern "C" void kernel_launch(void* const* d_in, const int* in_sizes, int n_in,
                              void* d_out, int out_size)
{
    const float* X      = (const float*)d_in[0];
    const float* tokW1  = (const float*)d_in[1];
    const float* tokb1  = (const float*)d_in[2];
    const float* tokW2  = (const float*)d_in[3];
    const float* tokb2  = (const float*)d_in[4];
    const float* ctxW1  = (const float*)d_in[5];
    const float* ctxb1  = (const float*)d_in[6];
    const float* ctxW2  = (const float*)d_in[7];
    const float* ctxb2  = (const float*)d_in[8];
    const float* taskW1 = (const float*)d_in[9];
    const float* taskb1 = (const float*)d_in[10];
    const float* taskW2 = (const float*)d_in[11];
    const float* taskb2 = (const float*)d_in[12];
    const float* effW1  = (const float*)d_in[13];
    const float* effb1  = (const float*)d_in[14];
    const float* effW2  = (const float*)d_in[15];
    const float* effb2  = (const float*)d_in[16];
    const float* supW1  = (const float*)d_in[17];
    const float* supb1  = (const float*)d_in[18];
    const float* supW2  = (const float*)d_in[19];
    const float* supb2  = (const float*)d_in[20];
    const float* depW1  = (const float*)d_in[21];
    const float* depb1  = (const float*)d_in[22];
    const float* depW2  = (const float*)d_in[23];
    const float* depb2  = (const float*)d_in[24];
    float* out = (float*)d_out;

    zero_scratch<<<512, 256>>>();
    mean_partial<<<512, 256>>>(X);
    ctx_task_kernel<<<dim3(BATCH, 2), 1024>>>(ctxW1, ctxb1, ctxW2, ctxb2,
                                              taskW1, taskb1, taskW2, taskb2, out);

    {
        dim3 g(HH / 64, M_ROWS / 128);
        mlp_gemm<1, false><<<g, 256>>>(X, tokW1, tokb1, tokW2, 0,
                                       nullptr, nullptr, nullptr, HH);
        mlp_gemm<1, false><<<g, 256>>>(X, effW1, effb1, effW2, 1,
                                       nullptr, nullptr, nullptr, HH);
    }
    finalize_tokeff<<<M_ROWS / 256, 256>>>(out, tokb2, effb2);

    {
        dim3 g(H / 64, M_ROWS / 128);
        mlp_gemm<SUPC, true><<<g, 256>>>(X, supW1, supb1, supW2, 2,
                                         out + OFF_TOK, out + OFF_CTX,
                                         out + OFF_TASK, H);
        mlp_gemm<HEADSC, true><<<g, 256>>>(X, depW1, depb1, depW2, 3,
                                           out + OFF_TOK, out + OFF_CTX,
                                           out + OFF_TASK, H);
    }
    softmax_mask<<<M_ROWS / 256, 256>>>(out, supb2, depb2);

    (void)in_sizes; (void)n_in; (void)out_size;
}

// round 5
// speedup vs baseline: 2.5321x; 2.5321x over previous
#include <cuda_runtime.h>
#include <cuda_fp16.h>
#include <cstdint>
#include <math.h>

#define H      2048
#define HH     1024
#define BATCH  4
#define SEQ    4096
#define M_ROWS 16384
#define SUPC   4
#define HEADSC 8

// d_out float offsets (tuple order, flattened)
#define OFF_TOK  0
#define OFF_CTX  16384
#define OFF_TASK 16388
#define OFF_SUP  16392
#define OFF_DEP  81928
#define OFF_EFF  213000
#define OFF_MASK 229384

// ================= scratch (no allocations allowed) =================
__device__ float g_ctxsum[BATCH * H];
__device__ float g_rowsum0[M_ROWS];
__device__ float g_rowsum1[M_ROWS];
__device__ float g_slog[M_ROWS * SUPC];
__device__ float g_dlog[M_ROWS * HEADSC];

// fp16 splits of X: [M_ROWS][H]
__device__ __half gX0[M_ROWS * H];
__device__ __half gX1[M_ROWS * H];
// transposed fp16 W1s: [N][2048] K-major
__device__ __half gWtok0[HH * H];
__device__ __half gWtok1[HH * H];
__device__ __half gWeff0[HH * H];
__device__ __half gWsup0[H * H];
__device__ __half gWsup1[H * H];
__device__ __half gWdep0[H * H];

__device__ __forceinline__ float gelu_exact(float x) {
    return 0.5f * x * (1.0f + erff(x * 0.70710678118654752f));
}
__device__ __forceinline__ float sigmoidf_(float x) {
    return 1.0f / (1.0f + expf(-x));
}
__device__ __forceinline__ uint32_t smem_to_u32(const void* p) {
    uint32_t a;
    asm("{ .reg .u64 t; cvta.to.shared.u64 t, %1; cvt.u32.u64 %0, t; }" : "=r"(a) : "l"(p));
    return a;
}
#define SWZ(off) ((off) ^ (((off) >> 3) & 0x70))

#define LDSM4(r, addr) \
    asm volatile("ldmatrix.sync.aligned.m8n8.x4.shared.b16 {%0,%1,%2,%3}, [%4];" \
                 : "=r"((r)[0]), "=r"((r)[1]), "=r"((r)[2]), "=r"((r)[3]) : "r"(addr))

static constexpr int ASZ_C = 128 * 128;   // 16KB: A part tile (128 rows x 64 fp16)
static constexpr int BSZ_C = 256 * 128;   // 32KB: B part tile (256 rows x 64 fp16)

__device__ __forceinline__ void mmas(float (&acc)[4][8][4],
                                     uint32_t (&a)[4][4], uint32_t (&b)[4][4]) {
    #pragma unroll
    for (int ms = 0; ms < 4; ms++)
        #pragma unroll
        for (int ns = 0; ns < 8; ns++) {
            uint32_t b0 = b[ns >> 1][ns & 1];
            uint32_t b1 = b[ns >> 1][2 + (ns & 1)];
            asm volatile(
                "mma.sync.aligned.m16n8k16.row.col.f32.f16.f16.f32 "
                "{%0,%1,%2,%3}, {%4,%5,%6,%7}, {%8,%9}, {%0,%1,%2,%3};"
                : "+f"(acc[ms][ns][0]), "+f"(acc[ms][ns][1]),
                  "+f"(acc[ms][ns][2]), "+f"(acc[ms][ns][3])
                : "r"(a[ms][0]), "r"(a[ms][1]), "r"(a[ms][2]), "r"(a[ms][3]),
                  "r"(b0), "r"(b1));
        }
}

// ================= precompute: split X into 2 fp16 parts =================
__global__ void split_x(const float* __restrict__ X) {
    size_t i = (size_t)blockIdx.x * blockDim.x + threadIdx.x;
    if (i >= (size_t)M_ROWS * H) return;
    float x = X[i];
    __half h = __float2half_rn(x);
    float r = x - __half2float(h);
    gX0[i] = h;
    gX1[i] = __float2half_rn(r);
}

// transpose W1 [K=2048 rows][N cols] -> Wt [N][2048] fp16, optional 2-split
__global__ void transpose_split_w(const float* __restrict__ W, int N, int nsplit,
                                  __half* __restrict__ o0, __half* __restrict__ o1) {
    __shared__ float t[32][33];
    int n0 = blockIdx.x * 32, k0 = blockIdx.y * 32;
    int tx = threadIdx.x & 31, ty = threadIdx.x >> 5;   // 256 threads: 32 x 8
    #pragma unroll
    for (int s = 0; s < 32; s += 8)
        t[ty + s][tx] = W[(size_t)(k0 + ty + s) * N + n0 + tx];
    __syncthreads();
    #pragma unroll
    for (int s = 0; s < 32; s += 8) {
        int n = n0 + ty + s, k = k0 + tx;
        float x = t[tx][ty + s];
        __half hh = __float2half_rn(x);
        o0[(size_t)n * H + k] = hh;
        if (nsplit == 2) {
            float r = x - __half2float(hh);
            o1[(size_t)n * H + k] = __float2half_rn(r);
        }
    }
}

// ================= zero scratch each launch =================
__global__ void zero_scratch() {
    int i = blockIdx.x * blockDim.x + threadIdx.x;
    if (i < BATCH * H)        g_ctxsum[i] = 0.f;
    if (i < M_ROWS)         { g_rowsum0[i] = 0.f; g_rowsum1[i] = 0.f; }
    if (i < M_ROWS * SUPC)    g_slog[i] = 0.f;
    if (i < M_ROWS * HEADSC)  g_dlog[i] = 0.f;
}

// ================= context mean partials =================
__global__ void mean_partial(const float* __restrict__ X) {
    int idx = blockIdx.x * blockDim.x + threadIdx.x;
    int d     = idx & (H - 1);
    int chunk = (idx >> 11) & 15;
    int b     = idx >> 15;
    const float* p = X + ((size_t)(b * SEQ + chunk * 256)) * H + d;
    float s = 0.f;
    #pragma unroll 8
    for (int t = 0; t < 256; t++) s += p[(size_t)t * H];
    atomicAdd(&g_ctxsum[b * H + d], s);
}

// ================= ctx / task MLPs =================
__global__ void ctx_task_kernel(
    const float* __restrict__ cW1, const float* __restrict__ cb1,
    const float* __restrict__ cW2, const float* __restrict__ cb2,
    const float* __restrict__ tW1, const float* __restrict__ tb1,
    const float* __restrict__ tW2, const float* __restrict__ tb2,
    float* __restrict__ out)
{
    __shared__ float emb[H];
    __shared__ float red[1024];
    int b = blockIdx.x, which = blockIdx.y;
    const float* W1 = which ? tW1 : cW1;
    const float* b1 = which ? tb1 : cb1;
    const float* W2 = which ? tW2 : cW2;
    const float* b2 = which ? tb2 : cb2;
    int tid = threadIdx.x;
    for (int i = tid; i < H; i += 1024)
        emb[i] = g_ctxsum[b * H + i] * (1.0f / SEQ);
    __syncthreads();

    float a = b1[tid];
    #pragma unroll 4
    for (int k = 0; k < H; k++)
        a = fmaf(emb[k], W1[(size_t)k * HH + tid], a);
    red[tid] = gelu_exact(a) * W2[tid];
    __syncthreads();
    for (int off = 512; off > 0; off >>= 1) {
        if (tid < off) red[tid] += red[tid + off];
        __syncthreads();
    }
    if (tid == 0)
        out[(which ? OFF_TASK : OFF_CTX) + b] = sigmoidf_(red[0] + b2[0]);
}

// ================= tensor-core fused MLP (mma.sync path) =================
// BM=128, BN=256, K-chunk 64 fp16 (128B swizzled rows). NT=1: single fp16 pass.
// NT=3: 2-way fp16 split terms A0B0 + A1B0 + A0B1 (near-fp32 accuracy).
template <int NA>
__device__ __forceinline__ void load_chunk(
    uint32_t dstbase, int kc, int m0, int n0, int tid,
    const __half* A0, const __half* A1,
    const __half* B0, const __half* B1)
{
    constexpr int ACH = NA * 1024;       // 16B chunks in A parts
    constexpr int TOT = ACH + NA * 2048; // + B parts
    for (int idx = tid; idx < TOT; idx += 256) {
        uint32_t dst;
        const __half* src;
        if (idx < ACH) {
            int s = idx >> 10;
            int r = (idx & 1023) >> 3;
            int i = idx & 7;
            dst = dstbase + s * ASZ_C + SWZ(r * 128 + i * 16);
            src = (s ? A1 : A0) + (size_t)(m0 + r) * H + kc * 64 + i * 8;
        } else {
            int j = idx - ACH;
            int s = j >> 11;
            int r = (j & 2047) >> 3;
            int i = j & 7;
            dst = dstbase + NA * ASZ_C + s * BSZ_C + SWZ(r * 128 + i * 16);
            src = (s ? B1 : B0) + (size_t)(n0 + r) * H + kc * 64 + i * 8;
        }
        asm volatile("cp.async.cg.shared.global [%0], [%1], 16;" :: "r"(dst), "l"(src) : "memory");
    }
    asm volatile("cp.async.commit_group;" ::: "memory");
}

template <int NT>
__device__ __forceinline__ void compute_chunk(
    uint32_t Ab, uint32_t Bb, float (&acc)[4][8][4], int wm, int wn, int lane)
{
    const int r16 = lane & 15;
    const int kg  = (lane >> 4) * 16;
    #pragma unroll
    for (int ks = 0; ks < 4; ks++) {
        const int kb = ks * 32 + kg;
        uint32_t af0[4][4], bf0[4][4];
        #pragma unroll
        for (int ms = 0; ms < 4; ms++)
            LDSM4(af0[ms], Ab + SWZ((wm * 64 + ms * 16 + r16) * 128 + kb));
        #pragma unroll
        for (int nt = 0; nt < 4; nt++)
            LDSM4(bf0[nt], Bb + SWZ((wn * 64 + nt * 16 + r16) * 128 + kb));
        mmas(acc, af0, bf0);
        if (NT == 3) {
            uint32_t af1[4][4];
            #pragma unroll
            for (int ms = 0; ms < 4; ms++)
                LDSM4(af1[ms], Ab + ASZ_C + SWZ((wm * 64 + ms * 16 + r16) * 128 + kb));
            mmas(acc, af1, bf0);
            uint32_t bf1[4][4];
            #pragma unroll
            for (int nt = 0; nt < 4; nt++)
                LDSM4(bf1[nt], Bb + BSZ_C + SWZ((wn * 64 + nt * 16 + r16) * 128 + kb));
            mmas(acc, af0, bf1);
        }
    }
}

template <int NT, int C, bool EX>
__global__ void __launch_bounds__(256, 1)
tc_gemm(const __half* __restrict__ A0, const __half* __restrict__ A1,
        const __half* __restrict__ B0, const __half* __restrict__ B1,
        const float* __restrict__ bias1, const float* __restrict__ W2,
        const float* __restrict__ W1orig, float* __restrict__ accout,
        const float* __restrict__ tcv, const float* __restrict__ ccv,
        const float* __restrict__ tkv, int Ntot)
{
    extern __shared__ char smem[];
    const uint32_t base = smem_to_u32(smem);
    constexpr int NA  = (NT == 3) ? 2 : 1;
    constexpr int STG = NA * (ASZ_C + BSZ_C);
    constexpr int NC  = H / 64;   // 32 chunks

    const int tid  = threadIdx.x;
    const int lane = tid & 31;
    const int wid  = tid >> 5;
    const int wm   = wid >> 2;    // 0..1  (64 rows each)
    const int wn   = wid & 3;     // 0..3  (64 cols each)
    const int m0   = blockIdx.y * 128;
    const int n0   = blockIdx.x * 256;

    float acc[4][8][4];
    #pragma unroll
    for (int a = 0; a < 4; a++)
        #pragma unroll
        for (int b = 0; b < 8; b++)
            #pragma unroll
            for (int c = 0; c < 4; c++) acc[a][b][c] = 0.f;

    load_chunk<NA>(base + 0 * STG, 0, m0, n0, tid, A0, A1, B0, B1);
    load_chunk<NA>(base + 1 * STG, 1, m0, n0, tid, A0, A1, B0, B1);

    for (int c = 0; c < NC; c++) {
        if (c < NC - 1) asm volatile("cp.async.wait_group %0;" :: "n"(1) : "memory");
        else            asm volatile("cp.async.wait_group %0;" :: "n"(0) : "memory");
        __syncthreads();
        const uint32_t sb = base + (c & 1) * STG;
        compute_chunk<NT>(sb, sb + NA * ASZ_C, acc, wm, wn, lane);
        __syncthreads();
        if (c + 2 < NC)
            load_chunk<NA>(sb, c + 2, m0, n0, tid, A0, A1, B0, B1);
    }

    // ---------------- epilogue ----------------
    float ccs = 0.f, tks = 0.f;
    if (EX) { ccs = ccv[m0 >> 12]; tks = tkv[m0 >> 12]; }

    #pragma unroll
    for (int ms = 0; ms < 4; ms++) {
        #pragma unroll
        for (int hh = 0; hh < 2; hh++) {
            const int r = m0 + wm * 64 + ms * 16 + (lane >> 2) + hh * 8;
            float tc = 0.f;
            if (EX) tc = tcv[r];
            float pc[C];
            #pragma unroll
            for (int ci = 0; ci < C; ci++) pc[ci] = 0.f;
            #pragma unroll
            for (int ns = 0; ns < 8; ns++) {
                #pragma unroll
                for (int e = 0; e < 2; e++) {
                    const int n = n0 + wn * 64 + ns * 8 + (lane & 3) * 2 + e;
                    float v = acc[ms][ns][hh * 2 + e] + bias1[n];
                    if (EX) {
                        v += tc  * W1orig[(size_t)2048 * Ntot + n]
                           + ccs * W1orig[(size_t)2049 * Ntot + n]
                           + tks * W1orig[(size_t)2050 * Ntot + n];
                    }
                    float h = gelu_exact(v);
                    #pragma unroll
                    for (int ci = 0; ci < C; ci++)
                        pc[ci] = fmaf(h, W2[(size_t)n * C + ci], pc[ci]);
                }
            }
            #pragma unroll
            for (int ci = 0; ci < C; ci++) {
                pc[ci] += __shfl_xor_sync(0xffffffffu, pc[ci], 1);
                pc[ci] += __shfl_xor_sync(0xffffffffu, pc[ci], 2);
            }
            if ((lane & 3) == 0) {
                #pragma unroll
                for (int ci = 0; ci < C; ci++)
                    atomicAdd(&accout[(size_t)r * C + ci], pc[ci]);
            }
        }
    }
}

// ================= tok/eff finalize =================
__global__ void finalize_tokeff(float* __restrict__ out,
                                const float* __restrict__ tokb2,
                                const float* __restrict__ effb2)
{
    int r = blockIdx.x * blockDim.x + threadIdx.x;
    if (r < M_ROWS) {
        out[OFF_TOK + r] = sigmoidf_(g_rowsum0[r] + tokb2[0]);
        out[OFF_EFF + r] = sigmoidf_(g_rowsum1[r] + effb2[0]);
    }
}

// ================= softmax + mask =================
__global__ void softmax_mask(float* __restrict__ out,
                             const float* __restrict__ supb2,
                             const float* __restrict__ depb2)
{
    int r = blockIdx.x * blockDim.x + threadIdx.x;
    if (r >= M_ROWS) return;
    {
        float l[SUPC];
        float m = -1e30f;
        #pragma unroll
        for (int c = 0; c < SUPC; c++) {
            l[c] = g_slog[(size_t)r * SUPC + c] + supb2[c];
            m = fmaxf(m, l[c]);
        }
        float s = 0.f;
        #pragma unroll
        for (int c = 0; c < SUPC; c++) { l[c] = expf(l[c] - m); s += l[c]; }
        float inv = 1.f / s;
        float eff = out[OFF_EFF + r];
        #pragma unroll
        for (int c = 0; c < SUPC; c++) {
            float w = l[c] * inv;
            out[OFF_SUP  + (size_t)r * SUPC + c] = w;
            out[OFF_MASK + (size_t)r * SUPC + c] = (w > 0.2f) ? eff : 0.f;
        }
    }
    {
        float l[HEADSC];
        float m = -1e30f;
        #pragma unroll
        for (int c = 0; c < HEADSC; c++) {
            l[c] = g_dlog[(size_t)r * HEADSC + c] + depb2[c];
            m = fmaxf(m, l[c]);
        }
        float s = 0.f;
        #pragma unroll
        for (int c = 0; c < HEADSC; c++) { l[c] = expf(l[c] - m); s += l[c]; }
        float inv = 1.f / s;
        #pragma unroll
        for (int c = 0; c < HEADSC; c++)
            out[OFF_DEP + (size_t)r * HEADSC + c] = l[c] * inv;
    }
}

// ================= launch =================
extern "C" void kernel_launch(void* const* d_in, const int* in_sizes, int n_in,
                              void* d_out, int out_size)
{
    const float* X      = (const float*)d_in[0];
    const float* tokW1  = (const float*)d_in[1];
    const float* tokb1  = (const float*)d_in[2];
    const float* tokW2  = (const float*)d_in[3];
    const float* tokb2  = (const float*)d_in[4];
    const float* ctxW1  = (const float*)d_in[5];
    const float* ctxb1  = (const float*)d_in[6];
    const float* ctxW2  = (const float*)d_in[7];
    const float* ctxb2  = (const float*)d_in[8];
    const float* taskW1 = (const float*)d_in[9];
    const float* taskb1 = (const float*)d_in[10];
    const float* taskW2 = (const float*)d_in[11];
    const float* taskb2 = (const float*)d_in[12];
    const float* effW1  = (const float*)d_in[13];
    const float* effb1  = (const float*)d_in[14];
    const float* effW2  = (const float*)d_in[15];
    const float* effb2  = (const float*)d_in[16];
    const float* supW1  = (const float*)d_in[17];
    const float* supb1  = (const float*)d_in[18];
    const float* supW2  = (const float*)d_in[19];
    const float* supb2  = (const float*)d_in[20];
    const float* depW1  = (const float*)d_in[21];
    const float* depb1  = (const float*)d_in[22];
    const float* depW2  = (const float*)d_in[23];
    const float* depb2  = (const float*)d_in[24];
    float* out = (float*)d_out;

    void *pX0, *pX1, *pWt0, *pWt1, *pWe0, *pWs0, *pWs1, *pWd0;
    void *pR0, *pR1, *pSL, *pDL;
    cudaGetSymbolAddress(&pX0, gX0);   cudaGetSymbolAddress(&pX1, gX1);
    cudaGetSymbolAddress(&pWt0, gWtok0); cudaGetSymbolAddress(&pWt1, gWtok1);
    cudaGetSymbolAddress(&pWe0, gWeff0);
    cudaGetSymbolAddress(&pWs0, gWsup0); cudaGetSymbolAddress(&pWs1, gWsup1);
    cudaGetSymbolAddress(&pWd0, gWdep0);
    cudaGetSymbolAddress(&pR0, g_rowsum0); cudaGetSymbolAddress(&pR1, g_rowsum1);
    cudaGetSymbolAddress(&pSL, g_slog);    cudaGetSymbolAddress(&pDL, g_dlog);

    constexpr int SM3 = 2 * (2 * ASZ_C + 2 * BSZ_C);   // 196608
    constexpr int SM1 = 2 * (ASZ_C + BSZ_C);           //  98304
    cudaFuncSetAttribute(tc_gemm<3, 1, false>,
                         cudaFuncAttributeMaxDynamicSharedMemorySize, SM3);
    cudaFuncSetAttribute(tc_gemm<1, 1, false>,
                         cudaFuncAttributeMaxDynamicSharedMemorySize, SM1);
    cudaFuncSetAttribute(tc_gemm<3, SUPC, true>,
                         cudaFuncAttributeMaxDynamicSharedMemorySize, SM3);
    cudaFuncSetAttribute(tc_gemm<1, HEADSC, true>,
                         cudaFuncAttributeMaxDynamicSharedMemorySize, SM1);

    zero_scratch<<<512, 256>>>();
    split_x<<<(M_ROWS * H) / 512, 512>>>(X);
    transpose_split_w<<<dim3(HH / 32, H / 32), 256>>>(tokW1, HH, 2,
        (__half*)pWt0, (__half*)pWt1);
    transpose_split_w<<<dim3(HH / 32, H / 32), 256>>>(effW1, HH, 1,
        (__half*)pWe0, (__half*)pWe0);
    transpose_split_w<<<dim3(H / 32, H / 32), 256>>>(supW1, H, 2,
        (__half*)pWs0, (__half*)pWs1);
    transpose_split_w<<<dim3(H / 32, H / 32), 256>>>(depW1, H, 1,
        (__half*)pWd0, (__half*)pWd0);

    mean_partial<<<512, 256>>>(X);
    ctx_task_kernel<<<dim3(BATCH, 2), 1024>>>(ctxW1, ctxb1, ctxW2, ctxb2,
                                              taskW1, taskb1, taskW2, taskb2, out);

    // tok: 3-term fp16 split (output + sup extra feature)
    tc_gemm<3, 1, false><<<dim3(HH / 256, M_ROWS / 128), 256, SM3>>>(
        (const __half*)pX0, (const __half*)pX1,
        (const __half*)pWt0, (const __half*)pWt1,
        tokb1, tokW2, nullptr, (float*)pR0, nullptr, nullptr, nullptr, HH);
    // eff: single-pass fp16 (continuous path)
    tc_gemm<1, 1, false><<<dim3(HH / 256, M_ROWS / 128), 256, SM1>>>(
        (const __half*)pX0, nullptr,
        (const __half*)pWe0, nullptr,
        effb1, effW2, nullptr, (float*)pR1, nullptr, nullptr, nullptr, HH);
    finalize_tokeff<<<M_ROWS / 256, 256>>>(out, tokb2, effb2);

    // sup: 3-term fp16 split (threshold-critical), extra features
    tc_gemm<3, SUPC, true><<<dim3(H / 256, M_ROWS / 128), 256, SM3>>>(
        (const __half*)pX0, (const __half*)pX1,
        (const __half*)pWs0, (const __half*)pWs1,
        supb1, supW2, supW1, (float*)pSL,
        out + OFF_TOK, out + OFF_CTX, out + OFF_TASK, H);
    // dep: single-pass fp16 (continuous path), extra features
    tc_gemm<1, HEADSC, true><<<dim3(H / 256, M_ROWS / 128), 256, SM1>>>(
        (const __half*)pX0, nullptr,
        (const __half*)pWd0, nullptr,
        depb1, depW2, depW1, (float*)pDL,
        out + OFF_TOK, out + OFF_CTX, out + OFF_TASK, H);
    softmax_mask<<<M_ROWS / 256, 256>>>(out, supb2, depb2);

    (void)in_sizes; (void)n_in; (void)out_size;
}

// round 6
// speedup vs baseline: 3.7699x; 1.4888x over previous
#include <cuda_runtime.h>
#include <cuda_fp16.h>
#include <cstdint>
#include <math.h>

#define H      2048
#define HH     1024
#define BATCH  4
#define SEQ    4096
#define M_ROWS 16384
#define SUPC   4
#define HEADSC 8

// d_out float offsets (tuple order, flattened)
#define OFF_TOK  0
#define OFF_CTX  16384
#define OFF_TASK 16388
#define OFF_SUP  16392
#define OFF_DEP  81928
#define OFF_EFF  213000
#define OFF_MASK 229384

#define RECHECK_MARGIN 0.005f

// ================= scratch (no allocations allowed) =================
__device__ float g_ctxsum[BATCH * H];
__device__ float g_rowsum0[M_ROWS];
__device__ float g_rowsum1[M_ROWS];
__device__ float g_slog[M_ROWS * SUPC];
__device__ float g_dlog[M_ROWS * HEADSC];
// recheck machinery
__device__ int   g_count;
__device__ int   g_rowmap[M_ROWS];
__device__ float g_rlog[M_ROWS * SUPC];

// fp16 splits of X: [M_ROWS][H]
__device__ __half gX0[M_ROWS * H];
__device__ __half gX1[M_ROWS * H];
// transposed fp16 W1s: [N][2048] K-major
__device__ __half gWtok0[HH * H];
__device__ __half gWeff0[HH * H];
__device__ __half gWsup0[H * H];
__device__ __half gWsup1[H * H];
__device__ __half gWdep0[H * H];

__device__ __forceinline__ float gelu_exact(float x) {
    return 0.5f * x * (1.0f + erff(x * 0.70710678118654752f));
}
__device__ __forceinline__ float sigmoidf_(float x) {
    return 1.0f / (1.0f + expf(-x));
}
__device__ __forceinline__ uint32_t smem_to_u32(const void* p) {
    uint32_t a;
    asm("{ .reg .u64 t; cvta.to.shared.u64 t, %1; cvt.u32.u64 %0, t; }" : "=r"(a) : "l"(p));
    return a;
}
#define SWZ(off) ((off) ^ (((off) >> 3) & 0x70))

#define LDSM4(r, addr) \
    asm volatile("ldmatrix.sync.aligned.m8n8.x4.shared.b16 {%0,%1,%2,%3}, [%4];" \
                 : "=r"((r)[0]), "=r"((r)[1]), "=r"((r)[2]), "=r"((r)[3]) : "r"(addr))

static constexpr int ASZ_C = 128 * 128;   // 16KB: A part tile (128 rows x 64 fp16)
static constexpr int BSZ_C = 256 * 128;   // 32KB: B part tile (256 rows x 64 fp16)

__device__ __forceinline__ void mmas(float (&acc)[4][8][4],
                                     uint32_t (&a)[4][4], uint32_t (&b)[4][4]) {
    #pragma unroll
    for (int ms = 0; ms < 4; ms++)
        #pragma unroll
        for (int ns = 0; ns < 8; ns++) {
            uint32_t b0 = b[ns >> 1][ns & 1];
            uint32_t b1 = b[ns >> 1][2 + (ns & 1)];
            asm volatile(
                "mma.sync.aligned.m16n8k16.row.col.f32.f16.f16.f32 "
                "{%0,%1,%2,%3}, {%4,%5,%6,%7}, {%8,%9}, {%0,%1,%2,%3};"
                : "+f"(acc[ms][ns][0]), "+f"(acc[ms][ns][1]),
                  "+f"(acc[ms][ns][2]), "+f"(acc[ms][ns][3])
                : "r"(a[ms][0]), "r"(a[ms][1]), "r"(a[ms][2]), "r"(a[ms][3]),
                  "r"(b0), "r"(b1));
        }
}

// ================= precompute: split X into 2 fp16 parts =================
__global__ void split_x(const float* __restrict__ X) {
    size_t i = (size_t)blockIdx.x * blockDim.x + threadIdx.x;
    if (i >= (size_t)M_ROWS * H) return;
    float x = X[i];
    __half h = __float2half_rn(x);
    float r = x - __half2float(h);
    gX0[i] = h;
    gX1[i] = __float2half_rn(r);
}

// transpose W1 [K=2048 rows][N cols] -> Wt [N][2048] fp16, optional 2-split
__global__ void transpose_split_w(const float* __restrict__ W, int N, int nsplit,
                                  __half* __restrict__ o0, __half* __restrict__ o1) {
    __shared__ float t[32][33];
    int n0 = blockIdx.x * 32, k0 = blockIdx.y * 32;
    int tx = threadIdx.x & 31, ty = threadIdx.x >> 5;   // 256 threads: 32 x 8
    #pragma unroll
    for (int s = 0; s < 32; s += 8)
        t[ty + s][tx] = W[(size_t)(k0 + ty + s) * N + n0 + tx];
    __syncthreads();
    #pragma unroll
    for (int s = 0; s < 32; s += 8) {
        int n = n0 + ty + s, k = k0 + tx;
        float x = t[tx][ty + s];
        __half hh = __float2half_rn(x);
        o0[(size_t)n * H + k] = hh;
        if (nsplit == 2) {
            float r = x - __half2float(hh);
            o1[(size_t)n * H + k] = __float2half_rn(r);
        }
    }
}

// ================= zero scratch each launch =================
__global__ void zero_scratch() {
    int i = blockIdx.x * blockDim.x + threadIdx.x;
    if (i == 0)               g_count = 0;
    if (i < BATCH * H)        g_ctxsum[i] = 0.f;
    if (i < M_ROWS)         { g_rowsum0[i] = 0.f; g_rowsum1[i] = 0.f; g_rowmap[i] = 0; }
    if (i < M_ROWS * SUPC)  { g_slog[i] = 0.f; g_rlog[i] = 0.f; }
    if (i < M_ROWS * HEADSC)  g_dlog[i] = 0.f;
}

// ================= context mean partials =================
__global__ void mean_partial(const float* __restrict__ X) {
    int idx = blockIdx.x * blockDim.x + threadIdx.x;
    int d     = idx & (H - 1);
    int chunk = (idx >> 11) & 15;
    int b     = idx >> 15;
    const float* p = X + ((size_t)(b * SEQ + chunk * 256)) * H + d;
    float s = 0.f;
    #pragma unroll 8
    for (int t = 0; t < 256; t++) s += p[(size_t)t * H];
    atomicAdd(&g_ctxsum[b * H + d], s);
}

// ================= ctx / task MLPs =================
__global__ void ctx_task_kernel(
    const float* __restrict__ cW1, const float* __restrict__ cb1,
    const float* __restrict__ cW2, const float* __restrict__ cb2,
    const float* __restrict__ tW1, const float* __restrict__ tb1,
    const float* __restrict__ tW2, const float* __restrict__ tb2,
    float* __restrict__ out)
{
    __shared__ float emb[H];
    __shared__ float red[1024];
    int b = blockIdx.x, which = blockIdx.y;
    const float* W1 = which ? tW1 : cW1;
    const float* b1 = which ? tb1 : cb1;
    const float* W2 = which ? tW2 : cW2;
    const float* b2 = which ? tb2 : cb2;
    int tid = threadIdx.x;
    for (int i = tid; i < H; i += 1024)
        emb[i] = g_ctxsum[b * H + i] * (1.0f / SEQ);
    __syncthreads();

    float a = b1[tid];
    #pragma unroll 4
    for (int k = 0; k < H; k++)
        a = fmaf(emb[k], W1[(size_t)k * HH + tid], a);
    red[tid] = gelu_exact(a) * W2[tid];
    __syncthreads();
    for (int off = 512; off > 0; off >>= 1) {
        if (tid < off) red[tid] += red[tid + off];
        __syncthreads();
    }
    if (tid == 0)
        out[(which ? OFF_TASK : OFF_CTX) + b] = sigmoidf_(red[0] + b2[0]);
}

// ================= tensor-core fused MLP (mma.sync path) =================
// BM=128, BN=256, K-chunk 64 fp16 (128B swizzled rows).
// NT=1: single fp16 pass (3-stage pipeline). NT=3: 2-way split terms
// A0B0+A1B0+A0B1 (near-fp32, 2-stage) -- used only for the gathered recheck.
// G: gather A rows through g_rowmap (recheck), compacted output slots.
template <int NA, bool G>
__device__ __forceinline__ void load_chunk(
    uint32_t dstbase, int kc, int m0, int tid, const int* rs,
    const __half* A0, const __half* A1,
    const __half* B0, const __half* B1)
{
    constexpr int ACH = NA * 1024;       // 16B chunks in A parts
    constexpr int TOT = ACH + NA * 2048; // + B parts
    for (int idx = tid; idx < TOT; idx += 256) {
        uint32_t dst;
        const __half* src;
        if (idx < ACH) {
            int s = idx >> 10;
            int r = (idx & 1023) >> 3;
            int i = idx & 7;
            int grow = G ? rs[r] : (m0 + r);
            dst = dstbase + s * ASZ_C + SWZ(r * 128 + i * 16);
            src = (s ? A1 : A0) + (size_t)grow * H + kc * 64 + i * 8;
        } else {
            int j = idx - ACH;
            int s = j >> 11;
            int r = (j & 2047) >> 3;
            int i = j & 7;
            dst = dstbase + NA * ASZ_C + s * BSZ_C + SWZ(r * 128 + i * 16);
            src = (s ? B1 : B0) + (size_t)((blockIdx.x * 256) + r) * H + kc * 64 + i * 8;
        }
        asm volatile("cp.async.cg.shared.global [%0], [%1], 16;" :: "r"(dst), "l"(src) : "memory");
    }
    asm volatile("cp.async.commit_group;" ::: "memory");
}

template <int NT>
__device__ __forceinline__ void compute_chunk(
    uint32_t Ab, uint32_t Bb, float (&acc)[4][8][4], int wm, int wn, int lane)
{
    const int r16 = lane & 15;
    const int kg  = (lane >> 4) * 16;
    #pragma unroll
    for (int ks = 0; ks < 4; ks++) {
        const int kb = ks * 32 + kg;
        uint32_t af0[4][4], bf0[4][4];
        #pragma unroll
        for (int ms = 0; ms < 4; ms++)
            LDSM4(af0[ms], Ab + SWZ((wm * 64 + ms * 16 + r16) * 128 + kb));
        #pragma unroll
        for (int nt = 0; nt < 4; nt++)
            LDSM4(bf0[nt], Bb + SWZ((wn * 64 + nt * 16 + r16) * 128 + kb));
        mmas(acc, af0, bf0);
        if (NT == 3) {
            uint32_t af1[4][4];
            #pragma unroll
            for (int ms = 0; ms < 4; ms++)
                LDSM4(af1[ms], Ab + ASZ_C + SWZ((wm * 64 + ms * 16 + r16) * 128 + kb));
            mmas(acc, af1, bf0);
            uint32_t bf1[4][4];
            #pragma unroll
            for (int nt = 0; nt < 4; nt++)
                LDSM4(bf1[nt], Bb + BSZ_C + SWZ((wn * 64 + nt * 16 + r16) * 128 + kb));
            mmas(acc, af0, bf1);
        }
    }
}

template <int NT, int C, bool EX, bool G>
__global__ void __launch_bounds__(256, 1)
tc_gemm(const __half* __restrict__ A0, const __half* __restrict__ A1,
        const __half* __restrict__ B0, const __half* __restrict__ B1,
        const float* __restrict__ bias1, const float* __restrict__ W2,
        const float* __restrict__ W1orig, float* __restrict__ accout,
        const float* __restrict__ tcv, const float* __restrict__ ccv,
        const float* __restrict__ tkv, int Ntot)
{
    extern __shared__ char smem[];
    __shared__ int rowsm[128];
    const uint32_t base = smem_to_u32(smem);
    constexpr int NA  = (NT == 3) ? 2 : 1;
    constexpr int STG = NA * (ASZ_C + BSZ_C);
    constexpr int S   = (NT == 1) ? 3 : 2;   // pipeline stages
    constexpr int NC  = H / 64;              // 32 chunks

    const int tid  = threadIdx.x;
    const int lane = tid & 31;
    const int wid  = tid >> 5;
    const int wm   = wid >> 2;    // 0..1  (64 rows each)
    const int wn   = wid & 3;     // 0..3  (64 cols each)
    const int m0   = blockIdx.y * 128;
    const int n0   = blockIdx.x * 256;

    if (G) {
        if (m0 >= g_count) return;            // uniform per block
        for (int i = tid; i < 128; i += 256) rowsm[i] = g_rowmap[m0 + i];
        __syncthreads();
    }

    float acc[4][8][4];
    #pragma unroll
    for (int a = 0; a < 4; a++)
        #pragma unroll
        for (int b = 0; b < 8; b++)
            #pragma unroll
            for (int c = 0; c < 4; c++) acc[a][b][c] = 0.f;

    #pragma unroll
    for (int s = 0; s < S - 1; s++)
        load_chunk<NA, G>(base + s * STG, s, m0, tid, rowsm, A0, A1, B0, B1);

    for (int c = 0; c < NC; c++) {
        if (c + S - 1 < NC)
            load_chunk<NA, G>(base + ((c + S - 1) % S) * STG, c + S - 1, m0, tid,
                              rowsm, A0, A1, B0, B1);
        if (c + S - 1 < NC)
            asm volatile("cp.async.wait_group %0;" :: "n"(S - 1) : "memory");
        else if (c + S - 2 < NC)
            asm volatile("cp.async.wait_group %0;" :: "n"((S - 2 >= 0) ? S - 2 : 0) : "memory");
        else
            asm volatile("cp.async.wait_group %0;" :: "n"(0) : "memory");
        __syncthreads();
        const uint32_t sb = base + (c % S) * STG;
        compute_chunk<NT>(sb, sb + NA * ASZ_C, acc, wm, wn, lane);
        __syncthreads();
    }

    // ---------------- epilogue ----------------
    #pragma unroll
    for (int ms = 0; ms < 4; ms++) {
        #pragma unroll
        for (int hh = 0; hh < 2; hh++) {
            const int slot = m0 + wm * 64 + ms * 16 + (lane >> 2) + hh * 8;
            const int rg   = G ? rowsm[slot - m0] : slot;
            float tc = 0.f, ccs = 0.f, tks = 0.f;
            if (EX) { tc = tcv[rg]; ccs = ccv[rg >> 12]; tks = tkv[rg >> 12]; }
            float pc[C];
            #pragma unroll
            for (int ci = 0; ci < C; ci++) pc[ci] = 0.f;
            #pragma unroll
            for (int ns = 0; ns < 8; ns++) {
                #pragma unroll
                for (int e = 0; e < 2; e++) {
                    const int n = n0 + wn * 64 + ns * 8 + (lane & 3) * 2 + e;
                    float v = acc[ms][ns][hh * 2 + e] + bias1[n];
                    if (EX) {
                        v += tc  * W1orig[(size_t)2048 * Ntot + n]
                           + ccs * W1orig[(size_t)2049 * Ntot + n]
                           + tks * W1orig[(size_t)2050 * Ntot + n];
                    }
                    float h = gelu_exact(v);
                    #pragma unroll
                    for (int ci = 0; ci < C; ci++)
                        pc[ci] = fmaf(h, W2[(size_t)n * C + ci], pc[ci]);
                }
            }
            #pragma unroll
            for (int ci = 0; ci < C; ci++) {
                pc[ci] += __shfl_xor_sync(0xffffffffu, pc[ci], 1);
                pc[ci] += __shfl_xor_sync(0xffffffffu, pc[ci], 2);
            }
            if ((lane & 3) == 0) {
                #pragma unroll
                for (int ci = 0; ci < C; ci++)
                    atomicAdd(&accout[(size_t)slot * C + ci], pc[ci]);
            }
        }
    }
}

// ================= tok/eff finalize =================
__global__ void finalize_tokeff(float* __restrict__ out,
                                const float* __restrict__ tokb2,
                                const float* __restrict__ effb2)
{
    int r = blockIdx.x * blockDim.x + threadIdx.x;
    if (r < M_ROWS) {
        out[OFF_TOK + r] = sigmoidf_(g_rowsum0[r] + tokb2[0]);
        out[OFF_EFF + r] = sigmoidf_(g_rowsum1[r] + effb2[0]);
    }
}

// ================= softmax + mask (+ flag near-threshold rows) =================
__global__ void softmax_mask(float* __restrict__ out,
                             const float* __restrict__ supb2,
                             const float* __restrict__ depb2)
{
    int r = blockIdx.x * blockDim.x + threadIdx.x;
    if (r >= M_ROWS) return;
    {
        float l[SUPC];
        float m = -1e30f;
        #pragma unroll
        for (int c = 0; c < SUPC; c++) {
            l[c] = g_slog[(size_t)r * SUPC + c] + supb2[c];
            m = fmaxf(m, l[c]);
        }
        float s = 0.f;
        #pragma unroll
        for (int c = 0; c < SUPC; c++) { l[c] = expf(l[c] - m); s += l[c]; }
        float inv = 1.f / s;
        float eff = out[OFF_EFF + r];
        bool flag = false;
        #pragma unroll
        for (int c = 0; c < SUPC; c++) {
            float w = l[c] * inv;
            if (fabsf(w - 0.2f) < RECHECK_MARGIN) flag = true;
            out[OFF_SUP  + (size_t)r * SUPC + c] = w;
            out[OFF_MASK + (size_t)r * SUPC + c] = (w > 0.2f) ? eff : 0.f;
        }
        if (flag) {
            int slot = atomicAdd(&g_count, 1);
            g_rowmap[slot] = r;
        }
    }
    {
        float l[HEADSC];
        float m = -1e30f;
        #pragma unroll
        for (int c = 0; c < HEADSC; c++) {
            l[c] = g_dlog[(size_t)r * HEADSC + c] + depb2[c];
            m = fmaxf(m, l[c]);
        }
        float s = 0.f;
        #pragma unroll
        for (int c = 0; c < HEADSC; c++) { l[c] = expf(l[c] - m); s += l[c]; }
        float inv = 1.f / s;
        #pragma unroll
        for (int c = 0; c < HEADSC; c++)
            out[OFF_DEP + (size_t)r * HEADSC + c] = l[c] * inv;
    }
}

// ================= recheck finalize: overwrite flagged rows =================
__global__ void recheck_final(float* __restrict__ out,
                              const float* __restrict__ supb2)
{
    int t = blockIdx.x * blockDim.x + threadIdx.x;
    if (t >= g_count) return;
    int r = g_rowmap[t];
    float l[SUPC];
    float m = -1e30f;
    #pragma unroll
    for (int c = 0; c < SUPC; c++) {
        l[c] = g_rlog[(size_t)t * SUPC + c] + supb2[c];
        m = fmaxf(m, l[c]);
    }
    float s = 0.f;
    #pragma unroll
    for (int c = 0; c < SUPC; c++) { l[c] = expf(l[c] - m); s += l[c]; }
    float inv = 1.f / s;
    float eff = out[OFF_EFF + r];
    #pragma unroll
    for (int c = 0; c < SUPC; c++) {
        float w = l[c] * inv;
        out[OFF_SUP  + (size_t)r * SUPC + c] = w;
        out[OFF_MASK + (size_t)r * SUPC + c] = (w > 0.2f) ? eff : 0.f;
    }
}

// ================= launch =================
extern "C" void kernel_launch(void* const* d_in, const int* in_sizes, int n_in,
                              void* d_out, int out_size)
{
    const float* X      = (const float*)d_in[0];
    const float* tokW1  = (const float*)d_in[1];
    const float* tokb1  = (const float*)d_in[2];
    const float* tokW2  = (const float*)d_in[3];
    const float* tokb2  = (const float*)d_in[4];
    const float* ctxW1  = (const float*)d_in[5];
    const float* ctxb1  = (const float*)d_in[6];
    const float* ctxW2  = (const float*)d_in[7];
    const float* ctxb2  = (const float*)d_in[8];
    const float* taskW1 = (const float*)d_in[9];
    const float* taskb1 = (const float*)d_in[10];
    const float* taskW2 = (const float*)d_in[11];
    const float* taskb2 = (const float*)d_in[12];
    const float* effW1  = (const float*)d_in[13];
    const float* effb1  = (const float*)d_in[14];
    const float* effW2  = (const float*)d_in[15];
    const float* effb2  = (const float*)d_in[16];
    const float* supW1  = (const float*)d_in[17];
    const float* supb1  = (const float*)d_in[18];
    const float* supW2  = (const float*)d_in[19];
    const float* supb2  = (const float*)d_in[20];
    const float* depW1  = (const float*)d_in[21];
    const float* depb1  = (const float*)d_in[22];
    const float* depW2  = (const float*)d_in[23];
    const float* depb2  = (const float*)d_in[24];
    float* out = (float*)d_out;

    void *pX0, *pX1, *pWt0, *pWe0, *pWs0, *pWs1, *pWd0;
    void *pR0, *pR1, *pSL, *pDL, *pRL;
    cudaGetSymbolAddress(&pX0, gX0);   cudaGetSymbolAddress(&pX1, gX1);
    cudaGetSymbolAddress(&pWt0, gWtok0);
    cudaGetSymbolAddress(&pWe0, gWeff0);
    cudaGetSymbolAddress(&pWs0, gWsup0); cudaGetSymbolAddress(&pWs1, gWsup1);
    cudaGetSymbolAddress(&pWd0, gWdep0);
    cudaGetSymbolAddress(&pR0, g_rowsum0); cudaGetSymbolAddress(&pR1, g_rowsum1);
    cudaGetSymbolAddress(&pSL, g_slog);    cudaGetSymbolAddress(&pDL, g_dlog);
    cudaGetSymbolAddress(&pRL, g_rlog);

    constexpr int SM1 = 3 * (ASZ_C + BSZ_C);       // 147456 (NT=1, 3 stages)
    constexpr int SM3 = 2 * 2 * (ASZ_C + BSZ_C);   // 196608 (NT=3, 2 stages)
    cudaFuncSetAttribute(tc_gemm<1, 1, false, false>,
                         cudaFuncAttributeMaxDynamicSharedMemorySize, SM1);
    cudaFuncSetAttribute(tc_gemm<1, SUPC, true, false>,
                         cudaFuncAttributeMaxDynamicSharedMemorySize, SM1);
    cudaFuncSetAttribute(tc_gemm<1, HEADSC, true, false>,
                         cudaFuncAttributeMaxDynamicSharedMemorySize, SM1);
    cudaFuncSetAttribute(tc_gemm<3, SUPC, true, true>,
                         cudaFuncAttributeMaxDynamicSharedMemorySize, SM3);

    zero_scratch<<<512, 256>>>();
    split_x<<<(M_ROWS * H) / 512, 512>>>(X);
    transpose_split_w<<<dim3(HH / 32, H / 32), 256>>>(tokW1, HH, 1,
        (__half*)pWt0, (__half*)pWt0);
    transpose_split_w<<<dim3(HH / 32, H / 32), 256>>>(effW1, HH, 1,
        (__half*)pWe0, (__half*)pWe0);
    transpose_split_w<<<dim3(H / 32, H / 32), 256>>>(supW1, H, 2,
        (__half*)pWs0, (__half*)pWs1);
    transpose_split_w<<<dim3(H / 32, H / 32), 256>>>(depW1, H, 1,
        (__half*)pWd0, (__half*)pWd0);

    mean_partial<<<512, 256>>>(X);
    ctx_task_kernel<<<dim3(BATCH, 2), 1024>>>(ctxW1, ctxb1, ctxW2, ctxb2,
                                              taskW1, taskb1, taskW2, taskb2, out);

    // tok / eff: single-pass fp16
    tc_gemm<1, 1, false, false><<<dim3(HH / 256, M_ROWS / 128), 256, SM1>>>(
        (const __half*)pX0, nullptr, (const __half*)pWt0, nullptr,
        tokb1, tokW2, nullptr, (float*)pR0, nullptr, nullptr, nullptr, HH);
    tc_gemm<1, 1, false, false><<<dim3(HH / 256, M_ROWS / 128), 256, SM1>>>(
        (const __half*)pX0, nullptr, (const __half*)pWe0, nullptr,
        effb1, effW2, nullptr, (float*)pR1, nullptr, nullptr, nullptr, HH);
    finalize_tokeff<<<M_ROWS / 256, 256>>>(out, tokb2, effb2);

    // sup / dep: single-pass fp16 with extra features
    tc_gemm<1, SUPC, true, false><<<dim3(H / 256, M_ROWS / 128), 256, SM1>>>(
        (const __half*)pX0, nullptr, (const __half*)pWs0, nullptr,
        supb1, supW2, supW1, (float*)pSL,
        out + OFF_TOK, out + OFF_CTX, out + OFF_TASK, H);
    tc_gemm<1, HEADSC, true, false><<<dim3(H / 256, M_ROWS / 128), 256, SM1>>>(
        (const __half*)pX0, nullptr, (const __half*)pWd0, nullptr,
        depb1, depW2, depW1, (float*)pDL,
        out + OFF_TOK, out + OFF_CTX, out + OFF_TASK, H);

    softmax_mask<<<M_ROWS / 256, 256>>>(out, supb2, depb2);

    // recheck: gathered 3-term split GEMM over flagged rows only (early-exit CTAs)
    tc_gemm<3, SUPC, true, true><<<dim3(H / 256, M_ROWS / 128), 256, SM3>>>(
        (const __half*)pX0, (const __half*)pX1,
        (const __half*)pWs0, (const __half*)pWs1,
        supb1, supW2, supW1, (float*)pRL,
        out + OFF_TOK, out + OFF_CTX, out + OFF_TASK, H);
    recheck_final<<<M_ROWS / 256, 256>>>(out, supb2);

    (void)in_sizes; (void)n_in; (void)out_size;
}